// round 4
// baseline (speedup 1.0000x reference)
#include <cuda_runtime.h>
#include <math.h>

#define BB 8
#define SS 2048
#define HH 1024
#define NN 262144
#define DD 512
#define KK 8

// ---------- scratch (device globals; no allocation allowed) ----------
__device__ float g_xpart[8 * BB * HH];      // [z][b][h] partial sums over S
__device__ float g_q[BB * DD];              // pooled (unnormalized) queries
__device__ float g_scores[NN * BB];         // [n][b] cosine scores
__device__ int   g_topk[BB * KK];           // [b][k] indices
__device__ float g_Rt[BB * DD * KK];        // [b][d][k] normalized retrieved rows (transposed)
__device__ float g_W2[BB * HH * KK];        // [b][h][k] = Wq @ R^T
__device__ float g_RO[BB * HH * KK];        // [b][h][k] = (R @ Wo) stored h-major
__device__ float g_attn[BB * SS * KK];      // [b][s][k] softmax weights

// ---------- Kernel A: partial sums of x over S ----------
__global__ void k_xpart(const float* __restrict__ x) {
    int h = blockIdx.x * 256 + threadIdx.x;  // grid.x = 4
    int b = blockIdx.y;                       // 8
    int z = blockIdx.z;                       // 8 s-chunks of 256
    const float* xp = x + ((size_t)b * SS + (size_t)z * 256) * HH + h;
    float s = 0.0f;
#pragma unroll 8
    for (int i = 0; i < 256; i++) s += xp[(size_t)i * HH];
    g_xpart[(z * BB + b) * HH + h] = s;
}

// ---------- Kernel B: q[b][d] = (sum_s x[b,s,:]) @ Wq ----------
__global__ void k_query(const float* __restrict__ Wq) {
    __shared__ float xs[HH];
    int b = blockIdx.y;
    for (int h = threadIdx.x; h < HH; h += 256) {
        float s = 0.0f;
#pragma unroll
        for (int z = 0; z < 8; z++) s += g_xpart[(z * BB + b) * HH + h];
        xs[h] = s;
    }
    __syncthreads();
    int d = blockIdx.x * 256 + threadIdx.x;  // grid.x = 2
    float acc = 0.0f;
#pragma unroll 4
    for (int h = 0; h < HH; h++) acc += xs[h] * Wq[(size_t)h * DD + d];
    g_q[b * DD + d] = acc;
}

// ---------- Kernel C: cosine scores over the 512MB archive (DRAM-bound) ----------
// warp handles 4 consecutive rows; on-the-fly row norms; 8 batch dots per row.
__global__ void __launch_bounds__(256) k_scores(const float* __restrict__ mem) {
    __shared__ float4 q_sh[BB * (DD / 4)];  // 16KB
    int tid = threadIdx.x;
    const float4* q4 = (const float4*)g_q;
    for (int i = tid; i < BB * DD / 4; i += 256) q_sh[i] = q4[i];
    __syncthreads();

    int lane = tid & 31, warp = tid >> 5;
    size_t row0 = ((size_t)blockIdx.x * 8 + warp) * 4;
    const float4* m4 = (const float4*)mem;

    float acc[4][8];
    float nrm[4];
#pragma unroll
    for (int r = 0; r < 4; r++) {
        nrm[r] = 0.0f;
#pragma unroll
        for (int b = 0; b < 8; b++) acc[r][b] = 0.0f;
    }

#pragma unroll
    for (int j = 0; j < 4; j++) {
        int d4 = lane + 32 * j;  // float4 index 0..127
        float4 m[4];
#pragma unroll
        for (int r = 0; r < 4; r++) m[r] = m4[(row0 + r) * (DD / 4) + d4];
#pragma unroll
        for (int r = 0; r < 4; r++)
            nrm[r] += m[r].x * m[r].x + m[r].y * m[r].y + m[r].z * m[r].z + m[r].w * m[r].w;
#pragma unroll
        for (int b = 0; b < 8; b++) {
            float4 qv = q_sh[b * (DD / 4) + d4];
#pragma unroll
            for (int r = 0; r < 4; r++)
                acc[r][b] += m[r].x * qv.x + m[r].y * qv.y + m[r].z * qv.z + m[r].w * qv.w;
        }
    }

#pragma unroll
    for (int off = 16; off; off >>= 1) {
#pragma unroll
        for (int r = 0; r < 4; r++) {
            nrm[r] += __shfl_down_sync(0xffffffffu, nrm[r], off);
#pragma unroll
            for (int b = 0; b < 8; b++)
                acc[r][b] += __shfl_down_sync(0xffffffffu, acc[r][b], off);
        }
    }
    if (lane == 0) {
#pragma unroll
        for (int r = 0; r < 4; r++) {
            float inv = 1.0f / (sqrtf(nrm[r]) + 1e-8f);
            float4* s4 = (float4*)&g_scores[(row0 + r) * 8];
            s4[0] = make_float4(acc[r][0] * inv, acc[r][1] * inv, acc[r][2] * inv, acc[r][3] * inv);
            s4[1] = make_float4(acc[r][4] * inv, acc[r][5] * inv, acc[r][6] * inv, acc[r][7] * inv);
        }
    }
}

// ---------- Kernel D: per-batch top-8 (register-resident sorted lists + smem tree merge) ----------
__global__ void __launch_bounds__(512) k_topk() {
    __shared__ float sv[512 * 8];
    __shared__ int   si[512 * 8];
    int b = blockIdx.x, tid = threadIdx.x;

    float vals[8];
    int idxs[8];
#pragma unroll
    for (int i = 0; i < 8; i++) { vals[i] = -3.4e38f; idxs[i] = 0; }
    float vmin = -3.4e38f;

    for (int n = tid; n < NN; n += 512) {
        float v = g_scores[(size_t)n * 8 + b];
        if (v > vmin) {
            vals[7] = v; idxs[7] = n;
#pragma unroll
            for (int p = 7; p >= 1; p--) {
                if (vals[p] > vals[p - 1]) {
                    float tv = vals[p]; vals[p] = vals[p - 1]; vals[p - 1] = tv;
                    int ti = idxs[p]; idxs[p] = idxs[p - 1]; idxs[p - 1] = ti;
                }
            }
            vmin = vals[7];
        }
    }
#pragma unroll
    for (int i = 0; i < 8; i++) { sv[tid * 8 + i] = vals[i]; si[tid * 8 + i] = idxs[i]; }

    for (int stride = 256; stride >= 1; stride >>= 1) {
        __syncthreads();
        if (tid < stride) {
            float ov[8]; int oi[8];
            int ia = 0, ib2 = 0;
#pragma unroll
            for (int o = 0; o < 8; o++) {
                float va = sv[tid * 8 + ia];
                float vb = sv[(tid + stride) * 8 + ib2];
                if (va >= vb) { ov[o] = va; oi[o] = si[tid * 8 + ia]; ia++; }
                else          { ov[o] = vb; oi[o] = si[(tid + stride) * 8 + ib2]; ib2++; }
            }
#pragma unroll
            for (int o = 0; o < 8; o++) { sv[tid * 8 + o] = ov[o]; si[tid * 8 + o] = oi[o]; }
        }
    }
    __syncthreads();
    if (tid < 8) g_topk[b * 8 + tid] = si[tid];
}

// ---------- Kernel E1: gather + normalize retrieved rows -> g_Rt [b][d][k] ----------
__global__ void k_gather(const float* __restrict__ mem) {
    int g = blockIdx.x;  // b*8+k, 64 blocks
    int b = g >> 3, k = g & 7;
    int row = g_topk[g];
    const float4* m4 = (const float4*)(mem + (size_t)row * DD);
    __shared__ float red[128];
    int tid = threadIdx.x;  // 128 threads
    float4 v = m4[tid];
    red[tid] = v.x * v.x + v.y * v.y + v.z * v.z + v.w * v.w;
    __syncthreads();
    for (int s = 64; s; s >>= 1) {
        if (tid < s) red[tid] += red[tid + s];
        __syncthreads();
    }
    float inv = 1.0f / (sqrtf(red[0]) + 1e-8f);
    int d0 = tid * 4;
    float* Rt = g_Rt + (size_t)b * DD * 8;
    Rt[(d0 + 0) * 8 + k] = v.x * inv;
    Rt[(d0 + 1) * 8 + k] = v.y * inv;
    Rt[(d0 + 2) * 8 + k] = v.z * inv;
    Rt[(d0 + 3) * 8 + k] = v.w * inv;
}

// ---------- Kernel E2: W2[b][h][k] = sum_d Wq[h][d] * R[b][k][d] ----------
__global__ void __launch_bounds__(256) k_w2(const float* __restrict__ Wq) {
    __shared__ float4 R_sh[DD * 2];  // [d] -> 2x float4 over k
    int b = blockIdx.y;
    const float4* Rt4 = (const float4*)(g_Rt + (size_t)b * DD * 8);
    for (int i = threadIdx.x; i < DD * 2; i += 256) R_sh[i] = Rt4[i];
    __syncthreads();

    int h = blockIdx.x * 256 + threadIdx.x;  // grid.x = 4
    const float4* wq4 = (const float4*)(Wq + (size_t)h * DD);
    float acc[8];
#pragma unroll
    for (int k = 0; k < 8; k++) acc[k] = 0.0f;
#pragma unroll 2
    for (int dd = 0; dd < DD / 4; dd++) {
        float4 w = wq4[dd];
        float wv[4] = {w.x, w.y, w.z, w.w};
#pragma unroll
        for (int c = 0; c < 4; c++) {
            float4 r0 = R_sh[(dd * 4 + c) * 2];
            float4 r1 = R_sh[(dd * 4 + c) * 2 + 1];
            acc[0] += wv[c] * r0.x; acc[1] += wv[c] * r0.y;
            acc[2] += wv[c] * r0.z; acc[3] += wv[c] * r0.w;
            acc[4] += wv[c] * r1.x; acc[5] += wv[c] * r1.y;
            acc[6] += wv[c] * r1.z; acc[7] += wv[c] * r1.w;
        }
    }
    float4* o = (float4*)(g_W2 + ((size_t)b * HH + h) * 8);
    o[0] = make_float4(acc[0], acc[1], acc[2], acc[3]);
    o[1] = make_float4(acc[4], acc[5], acc[6], acc[7]);
}

// ---------- Kernel E3: RO[b][h][k] = sum_d R[b][k][d] * Wo[d][h] ----------
__global__ void __launch_bounds__(256) k_ro(const float* __restrict__ Wo) {
    __shared__ float4 R_sh[DD * 2];
    int b = blockIdx.y;
    const float4* Rt4 = (const float4*)(g_Rt + (size_t)b * DD * 8);
    for (int i = threadIdx.x; i < DD * 2; i += 256) R_sh[i] = Rt4[i];
    __syncthreads();

    int h = blockIdx.x * 256 + threadIdx.x;
    float acc[8];
#pragma unroll
    for (int k = 0; k < 8; k++) acc[k] = 0.0f;
#pragma unroll 4
    for (int d = 0; d < DD; d++) {
        float wo = Wo[(size_t)d * HH + h];
        float4 r0 = R_sh[d * 2];
        float4 r1 = R_sh[d * 2 + 1];
        acc[0] += wo * r0.x; acc[1] += wo * r0.y; acc[2] += wo * r0.z; acc[3] += wo * r0.w;
        acc[4] += wo * r1.x; acc[5] += wo * r1.y; acc[6] += wo * r1.z; acc[7] += wo * r1.w;
    }
    float4* o = (float4*)(g_RO + ((size_t)b * HH + h) * 8);
    o[0] = make_float4(acc[0], acc[1], acc[2], acc[3]);
    o[1] = make_float4(acc[4], acc[5], acc[6], acc[7]);
}

// ---------- Kernel F1: logits = x @ W2 / sqrt(D), softmax -> g_attn ----------
__global__ void __launch_bounds__(256) k_attn(const float* __restrict__ x) {
    __shared__ float W2p[HH * 9];  // padded stride 9 -> conflict-free
    int b = blockIdx.y;
    const float* W2g = g_W2 + (size_t)b * HH * 8;
    for (int i = threadIdx.x; i < HH * 8; i += 256) {
        int h = i >> 3, k = i & 7;
        W2p[h * 9 + k] = W2g[i];
    }
    __syncthreads();

    int lane = threadIdx.x & 31, warp = threadIdx.x >> 5;
    int tok0 = blockIdx.x * 64 + warp * 8;  // grid.x = 32
    const float* xb = x + ((size_t)b * SS + tok0) * HH;

    float lp[8][8];
#pragma unroll
    for (int t = 0; t < 8; t++)
#pragma unroll
        for (int k = 0; k < 8; k++) lp[t][k] = 0.0f;

#pragma unroll 4
    for (int i = 0; i < 32; i++) {
        int h = lane + 32 * i;
        float w2v[8];
#pragma unroll
        for (int k = 0; k < 8; k++) w2v[k] = W2p[h * 9 + k];
#pragma unroll
        for (int t = 0; t < 8; t++) {
            float xv = xb[(size_t)t * HH + h];
#pragma unroll
            for (int k = 0; k < 8; k++) lp[t][k] += xv * w2v[k];
        }
    }
#pragma unroll
    for (int off = 16; off; off >>= 1)
#pragma unroll
        for (int t = 0; t < 8; t++)
#pragma unroll
            for (int k = 0; k < 8; k++)
                lp[t][k] += __shfl_xor_sync(0xffffffffu, lp[t][k], off);

    const float scale = 0.044194173824159216f;  // 1/sqrt(512)
#pragma unroll
    for (int t = 0; t < 8; t++) {
        float l[8];
        float m = -3.4e38f;
#pragma unroll
        for (int k = 0; k < 8; k++) { l[k] = lp[t][k] * scale; m = fmaxf(m, l[k]); }
        float s = 0.0f;
#pragma unroll
        for (int k = 0; k < 8; k++) { l[k] = __expf(l[k] - m); s += l[k]; }
        float inv = 1.0f / s;
        if (lane == t) {
            float4* a4 = (float4*)(g_attn + ((size_t)b * SS + tok0 + t) * 8);
            a4[0] = make_float4(l[0] * inv, l[1] * inv, l[2] * inv, l[3] * inv);
            a4[1] = make_float4(l[4] * inv, l[5] * inv, l[6] * inv, l[7] * inv);
        }
    }
}

// ---------- Kernel F2: out = x + attn @ RO ----------
__global__ void __launch_bounds__(256) k_out(const float* __restrict__ x,
                                             float* __restrict__ out) {
    __shared__ float ROp[HH * 9];
    __shared__ float attn_sh[64 * 8];
    int b = blockIdx.y;
    const float* ROg = g_RO + (size_t)b * HH * 8;
    for (int i = threadIdx.x; i < HH * 8; i += 256) {
        int h = i >> 3, k = i & 7;
        ROp[h * 9 + k] = ROg[i];
    }
    int tokblk = blockIdx.x * 64;
    for (int i = threadIdx.x; i < 64 * 8; i += 256)
        attn_sh[i] = g_attn[((size_t)b * SS + tokblk) * 8 + i];
    __syncthreads();

    int lane = threadIdx.x & 31, warp = threadIdx.x >> 5;
    int tok0 = warp * 8;
    float att[8][8];
#pragma unroll
    for (int t = 0; t < 8; t++)
#pragma unroll
        for (int k = 0; k < 8; k++) att[t][k] = attn_sh[(tok0 + t) * 8 + k];

    const float* xb = x + ((size_t)b * SS + tokblk + tok0) * HH;
    float* ob = out + ((size_t)b * SS + tokblk + tok0) * HH;

#pragma unroll 2
    for (int i = 0; i < 32; i++) {
        int h = lane + 32 * i;
        float ro[8];
#pragma unroll
        for (int k = 0; k < 8; k++) ro[k] = ROp[h * 9 + k];
#pragma unroll
        for (int t = 0; t < 8; t++) {
            float o = xb[(size_t)t * HH + h];
#pragma unroll
            for (int k = 0; k < 8; k++) o += att[t][k] * ro[k];
            ob[(size_t)t * HH + h] = o;
        }
    }
}

// ---------- launch ----------
extern "C" void kernel_launch(void* const* d_in, const int* in_sizes, int n_in,
                              void* d_out, int out_size) {
    const float* x   = (const float*)d_in[0];
    const float* mem = (const float*)d_in[1];
    const float* Wq  = (const float*)d_in[2];
    const float* Wo  = (const float*)d_in[3];
    // d_in[4] = top_k (always 8; hardcoded)
    float* out = (float*)d_out;

    k_xpart <<<dim3(4, 8, 8), 256>>>(x);
    k_query <<<dim3(2, 8),    256>>>(Wq);
    k_scores<<<8192,          256>>>(mem);
    k_topk  <<<8,             512>>>();
    k_gather<<<64,            128>>>(mem);
    k_w2    <<<dim3(4, 8),    256>>>(Wq);
    k_ro    <<<dim3(4, 8),    256>>>(Wo);
    k_attn  <<<dim3(32, 8),   256>>>(x);
    k_out   <<<dim3(32, 8),   256>>>(x, out);
}

// round 5
// speedup vs baseline: 1.1413x; 1.1413x over previous
#include <cuda_runtime.h>
#include <math.h>

#define BB 8
#define SS 2048
#define HH 1024
#define NN 262144
#define DD 512
#define KK 8
#define TKB 128   // top-k stage-1 blocks per batch

// ---------- scratch (device globals; no allocation allowed) ----------
__device__ float g_xpart[8 * BB * HH];      // [z][b][h] partial sums over S
__device__ float g_q[BB * DD];              // pooled (unnormalized) queries
__device__ float g_scores[NN * BB];         // [n][b] cosine scores
__device__ int   g_topk[BB * KK];           // [b][k] indices
__device__ float g_cand_v[BB * TKB * 8];    // stage-1 candidate values
__device__ int   g_cand_i[BB * TKB * 8];    // stage-1 candidate indices
__device__ float g_Rt[BB * DD * KK];        // [b][d][k] normalized retrieved rows (transposed)
__device__ float g_W2[BB * HH * KK];        // [b][h][k] = Wq @ R^T
__device__ float g_RO[BB * HH * KK];        // [b][h][k] = (R @ Wo) stored h-major
__device__ float g_attn[BB * SS * KK];      // [b][s][k] softmax weights

// ---------- packed fp32x2 helpers (sm_100+; ptxas never auto-fuses these) ----------
__device__ __forceinline__ unsigned long long pack2(float lo, float hi) {
    unsigned long long r;
    asm("mov.b64 %0, {%1, %2};" : "=l"(r)
        : "r"(__float_as_uint(lo)), "r"(__float_as_uint(hi)));
    return r;
}
__device__ __forceinline__ void fma2(unsigned long long& d,
                                     unsigned long long a, unsigned long long b) {
    asm("fma.rn.f32x2 %0, %1, %2, %0;" : "+l"(d) : "l"(a), "l"(b));
}
__device__ __forceinline__ void unpack2(unsigned long long v, float& lo, float& hi) {
    unsigned int l, h;
    asm("mov.b64 {%0, %1}, %2;" : "=r"(l), "=r"(h) : "l"(v));
    lo = __uint_as_float(l); hi = __uint_as_float(h);
}

// ---------- Kernel A: partial sums of x over S ----------
__global__ void k_xpart(const float* __restrict__ x) {
    int h = blockIdx.x * 256 + threadIdx.x;  // grid.x = 4
    int b = blockIdx.y;                       // 8
    int z = blockIdx.z;                       // 8 s-chunks of 256
    const float* xp = x + ((size_t)b * SS + (size_t)z * 256) * HH + h;
    float s = 0.0f;
#pragma unroll 8
    for (int i = 0; i < 256; i++) s += xp[(size_t)i * HH];
    g_xpart[(z * BB + b) * HH + h] = s;
}

// ---------- Kernel B: q[b][d] = (sum_s x[b,s,:]) @ Wq ----------
__global__ void k_query(const float* __restrict__ Wq) {
    __shared__ float xs[HH];
    int b = blockIdx.y;
    for (int h = threadIdx.x; h < HH; h += 256) {
        float s = 0.0f;
#pragma unroll
        for (int z = 0; z < 8; z++) s += g_xpart[(z * BB + b) * HH + h];
        xs[h] = s;
    }
    __syncthreads();
    int d = blockIdx.x * 256 + threadIdx.x;  // grid.x = 2
    float acc = 0.0f;
#pragma unroll 4
    for (int h = 0; h < HH; h++) acc += xs[h] * Wq[(size_t)h * DD + d];
    g_q[b * DD + d] = acc;
}

// ---------- Kernel C: cosine scores over the 512MB archive ----------
// warp handles 4 rows; batch-PAIR-packed f32x2 accumulators halve fp32-pipe ops.
// q2_sh layout [bp][c][d4] (u64 = (q[2bp][d],q[2bp+1][d])) -> LDS.64, conflict-free.
__global__ void __launch_bounds__(256) k_scores(const float* __restrict__ mem) {
    __shared__ unsigned long long q2_sh[4 * 4 * 128];  // 16KB
    int tid = threadIdx.x;
    for (int i = tid; i < 2048; i += 256) {
        int d4 = i & 127;
        int c  = (i >> 7) & 3;
        int bp = i >> 9;
        int d  = d4 * 4 + c;
        q2_sh[i] = pack2(g_q[(2 * bp) * DD + d], g_q[(2 * bp + 1) * DD + d]);
    }
    __syncthreads();

    int lane = tid & 31, warp = tid >> 5;
    size_t row0 = ((size_t)blockIdx.x * 8 + warp) * 4;
    const float4* m4 = (const float4*)mem;

    unsigned long long acc2[4][4];  // [row][batch-pair]
    float nrm[4];
#pragma unroll
    for (int r = 0; r < 4; r++) {
        nrm[r] = 0.0f;
#pragma unroll
        for (int bp = 0; bp < 4; bp++) acc2[r][bp] = 0ull;
    }

#pragma unroll 2
    for (int j = 0; j < 4; j++) {
        int d4 = lane + 32 * j;  // float4 index 0..127
        float4 m[4];
#pragma unroll
        for (int r = 0; r < 4; r++) m[r] = m4[(row0 + r) * (DD / 4) + d4];
#pragma unroll
        for (int r = 0; r < 4; r++)
            nrm[r] += m[r].x * m[r].x + m[r].y * m[r].y + m[r].z * m[r].z + m[r].w * m[r].w;

        // duplicate m per row/component once, reuse across 4 batch pairs
        unsigned long long md[4][4];
#pragma unroll
        for (int r = 0; r < 4; r++) {
            md[r][0] = pack2(m[r].x, m[r].x);
            md[r][1] = pack2(m[r].y, m[r].y);
            md[r][2] = pack2(m[r].z, m[r].z);
            md[r][3] = pack2(m[r].w, m[r].w);
        }
#pragma unroll
        for (int bp = 0; bp < 4; bp++) {
            unsigned long long q0 = q2_sh[(bp * 4 + 0) * 128 + d4];
            unsigned long long q1 = q2_sh[(bp * 4 + 1) * 128 + d4];
            unsigned long long q2 = q2_sh[(bp * 4 + 2) * 128 + d4];
            unsigned long long q3 = q2_sh[(bp * 4 + 3) * 128 + d4];
#pragma unroll
            for (int r = 0; r < 4; r++) {
                fma2(acc2[r][bp], md[r][0], q0);
                fma2(acc2[r][bp], md[r][1], q1);
                fma2(acc2[r][bp], md[r][2], q2);
                fma2(acc2[r][bp], md[r][3], q3);
            }
        }
    }

    float acc[4][8];
#pragma unroll
    for (int r = 0; r < 4; r++)
#pragma unroll
        for (int bp = 0; bp < 4; bp++)
            unpack2(acc2[r][bp], acc[r][2 * bp], acc[r][2 * bp + 1]);

#pragma unroll
    for (int off = 16; off; off >>= 1) {
#pragma unroll
        for (int r = 0; r < 4; r++) {
            nrm[r] += __shfl_down_sync(0xffffffffu, nrm[r], off);
#pragma unroll
            for (int b = 0; b < 8; b++)
                acc[r][b] += __shfl_down_sync(0xffffffffu, acc[r][b], off);
        }
    }
    if (lane == 0) {
#pragma unroll
        for (int r = 0; r < 4; r++) {
            float inv = 1.0f / (sqrtf(nrm[r]) + 1e-8f);
            float4* s4 = (float4*)&g_scores[(row0 + r) * 8];
            s4[0] = make_float4(acc[r][0] * inv, acc[r][1] * inv, acc[r][2] * inv, acc[r][3] * inv);
            s4[1] = make_float4(acc[r][4] * inv, acc[r][5] * inv, acc[r][6] * inv, acc[r][7] * inv);
        }
    }
}

// ---------- Kernel D1: stage-1 top-8 (128 slices x 8 batches = 1024 blocks) ----------
__global__ void __launch_bounds__(256) k_topk1() {
    __shared__ float sv[256 * 8];
    __shared__ int   si[256 * 8];
    int b = blockIdx.y, blk = blockIdx.x, tid = threadIdx.x;
    int base = blk * (NN / TKB);  // 2048 rows per block

    float vals[8];
    int idxs[8];
#pragma unroll
    for (int i = 0; i < 8; i++) { vals[i] = -3.4e38f; idxs[i] = 0; }
    float vmin = -3.4e38f;

#pragma unroll 2
    for (int i = tid; i < NN / TKB; i += 256) {
        int n = base + i;
        float v = g_scores[(size_t)n * 8 + b];
        if (v > vmin) {
            vals[7] = v; idxs[7] = n;
#pragma unroll
            for (int p = 7; p >= 1; p--) {
                if (vals[p] > vals[p - 1]) {
                    float tv = vals[p]; vals[p] = vals[p - 1]; vals[p - 1] = tv;
                    int ti = idxs[p]; idxs[p] = idxs[p - 1]; idxs[p - 1] = ti;
                }
            }
            vmin = vals[7];
        }
    }
#pragma unroll
    for (int i = 0; i < 8; i++) { sv[tid * 8 + i] = vals[i]; si[tid * 8 + i] = idxs[i]; }

    for (int stride = 128; stride >= 1; stride >>= 1) {
        __syncthreads();
        if (tid < stride) {
            float ov[8]; int oi[8];
            int ia = 0, ib2 = 0;
#pragma unroll
            for (int o = 0; o < 8; o++) {
                float va = sv[tid * 8 + ia];
                float vb = sv[(tid + stride) * 8 + ib2];
                if (va >= vb) { ov[o] = va; oi[o] = si[tid * 8 + ia]; ia++; }
                else          { ov[o] = vb; oi[o] = si[(tid + stride) * 8 + ib2]; ib2++; }
            }
#pragma unroll
            for (int o = 0; o < 8; o++) { sv[tid * 8 + o] = ov[o]; si[tid * 8 + o] = oi[o]; }
        }
    }
    __syncthreads();
    if (tid < 8) {
        g_cand_v[(b * TKB + blk) * 8 + tid] = sv[tid];
        g_cand_i[(b * TKB + blk) * 8 + tid] = si[tid];
    }
}

// ---------- Kernel D2: stage-2 merge of 128 sorted candidate lists per batch ----------
__global__ void __launch_bounds__(128) k_topk2() {
    __shared__ float sv[128 * 8];
    __shared__ int   si[128 * 8];
    int b = blockIdx.x, tid = threadIdx.x;
#pragma unroll
    for (int i = 0; i < 8; i++) {
        sv[tid * 8 + i] = g_cand_v[(b * TKB + tid) * 8 + i];
        si[tid * 8 + i] = g_cand_i[(b * TKB + tid) * 8 + i];
    }
    for (int stride = 64; stride >= 1; stride >>= 1) {
        __syncthreads();
        if (tid < stride) {
            float ov[8]; int oi[8];
            int ia = 0, ib2 = 0;
#pragma unroll
            for (int o = 0; o < 8; o++) {
                float va = sv[tid * 8 + ia];
                float vb = sv[(tid + stride) * 8 + ib2];
                if (va >= vb) { ov[o] = va; oi[o] = si[tid * 8 + ia]; ia++; }
                else          { ov[o] = vb; oi[o] = si[(tid + stride) * 8 + ib2]; ib2++; }
            }
#pragma unroll
            for (int o = 0; o < 8; o++) { sv[tid * 8 + o] = ov[o]; si[tid * 8 + o] = oi[o]; }
        }
    }
    __syncthreads();
    if (tid < 8) g_topk[b * 8 + tid] = si[tid];
}

// ---------- Kernel E1: gather + normalize retrieved rows -> g_Rt [b][d][k] ----------
__global__ void k_gather(const float* __restrict__ mem) {
    int g = blockIdx.x;  // b*8+k, 64 blocks
    int b = g >> 3, k = g & 7;
    int row = g_topk[g];
    const float4* m4 = (const float4*)(mem + (size_t)row * DD);
    __shared__ float red[128];
    int tid = threadIdx.x;  // 128 threads
    float4 v = m4[tid];
    red[tid] = v.x * v.x + v.y * v.y + v.z * v.z + v.w * v.w;
    __syncthreads();
    for (int s = 64; s; s >>= 1) {
        if (tid < s) red[tid] += red[tid + s];
        __syncthreads();
    }
    float inv = 1.0f / (sqrtf(red[0]) + 1e-8f);
    int d0 = tid * 4;
    float* Rt = g_Rt + (size_t)b * DD * 8;
    Rt[(d0 + 0) * 8 + k] = v.x * inv;
    Rt[(d0 + 1) * 8 + k] = v.y * inv;
    Rt[(d0 + 2) * 8 + k] = v.z * inv;
    Rt[(d0 + 3) * 8 + k] = v.w * inv;
}

// ---------- Kernel E2: W2[b][h][k] = sum_d Wq[h][d] * R[b][k][d] ----------
__global__ void __launch_bounds__(256) k_w2(const float* __restrict__ Wq) {
    __shared__ float4 R_sh[DD * 2];  // [d] -> 2x float4 over k
    int b = blockIdx.y;
    const float4* Rt4 = (const float4*)(g_Rt + (size_t)b * DD * 8);
    for (int i = threadIdx.x; i < DD * 2; i += 256) R_sh[i] = Rt4[i];
    __syncthreads();

    int h = blockIdx.x * 256 + threadIdx.x;  // grid.x = 4
    const float4* wq4 = (const float4*)(Wq + (size_t)h * DD);
    float acc[8];
#pragma unroll
    for (int k = 0; k < 8; k++) acc[k] = 0.0f;
#pragma unroll 2
    for (int dd = 0; dd < DD / 4; dd++) {
        float4 w = wq4[dd];
        float wv[4] = {w.x, w.y, w.z, w.w};
#pragma unroll
        for (int c = 0; c < 4; c++) {
            float4 r0 = R_sh[(dd * 4 + c) * 2];
            float4 r1 = R_sh[(dd * 4 + c) * 2 + 1];
            acc[0] += wv[c] * r0.x; acc[1] += wv[c] * r0.y;
            acc[2] += wv[c] * r0.z; acc[3] += wv[c] * r0.w;
            acc[4] += wv[c] * r1.x; acc[5] += wv[c] * r1.y;
            acc[6] += wv[c] * r1.z; acc[7] += wv[c] * r1.w;
        }
    }
    float4* o = (float4*)(g_W2 + ((size_t)b * HH + h) * 8);
    o[0] = make_float4(acc[0], acc[1], acc[2], acc[3]);
    o[1] = make_float4(acc[4], acc[5], acc[6], acc[7]);
}

// ---------- Kernel E3: RO[b][h][k] = sum_d R[b][k][d] * Wo[d][h] ----------
__global__ void __launch_bounds__(256) k_ro(const float* __restrict__ Wo) {
    __shared__ float4 R_sh[DD * 2];
    int b = blockIdx.y;
    const float4* Rt4 = (const float4*)(g_Rt + (size_t)b * DD * 8);
    for (int i = threadIdx.x; i < DD * 2; i += 256) R_sh[i] = Rt4[i];
    __syncthreads();

    int h = blockIdx.x * 256 + threadIdx.x;
    float acc[8];
#pragma unroll
    for (int k = 0; k < 8; k++) acc[k] = 0.0f;
#pragma unroll 4
    for (int d = 0; d < DD; d++) {
        float wo = Wo[(size_t)d * HH + h];
        float4 r0 = R_sh[d * 2];
        float4 r1 = R_sh[d * 2 + 1];
        acc[0] += wo * r0.x; acc[1] += wo * r0.y; acc[2] += wo * r0.z; acc[3] += wo * r0.w;
        acc[4] += wo * r1.x; acc[5] += wo * r1.y; acc[6] += wo * r1.z; acc[7] += wo * r1.w;
    }
    float4* o = (float4*)(g_RO + ((size_t)b * HH + h) * 8);
    o[0] = make_float4(acc[0], acc[1], acc[2], acc[3]);
    o[1] = make_float4(acc[4], acc[5], acc[6], acc[7]);
}

// ---------- Kernel F1: logits = x @ W2 / sqrt(D), softmax -> g_attn ----------
__global__ void __launch_bounds__(256) k_attn(const float* __restrict__ x) {
    __shared__ float W2p[HH * 9];  // padded stride 9 -> conflict-free
    int b = blockIdx.y;
    const float* W2g = g_W2 + (size_t)b * HH * 8;
    for (int i = threadIdx.x; i < HH * 8; i += 256) {
        int h = i >> 3, k = i & 7;
        W2p[h * 9 + k] = W2g[i];
    }
    __syncthreads();

    int lane = threadIdx.x & 31, warp = threadIdx.x >> 5;
    int tok0 = blockIdx.x * 64 + warp * 8;  // grid.x = 32
    const float* xb = x + ((size_t)b * SS + tok0) * HH;

    float lp[8][8];
#pragma unroll
    for (int t = 0; t < 8; t++)
#pragma unroll
        for (int k = 0; k < 8; k++) lp[t][k] = 0.0f;

#pragma unroll 4
    for (int i = 0; i < 32; i++) {
        int h = lane + 32 * i;
        float w2v[8];
#pragma unroll
        for (int k = 0; k < 8; k++) w2v[k] = W2p[h * 9 + k];
#pragma unroll
        for (int t = 0; t < 8; t++) {
            float xv = xb[(size_t)t * HH + h];
#pragma unroll
            for (int k = 0; k < 8; k++) lp[t][k] += xv * w2v[k];
        }
    }
#pragma unroll
    for (int off = 16; off; off >>= 1)
#pragma unroll
        for (int t = 0; t < 8; t++)
#pragma unroll
            for (int k = 0; k < 8; k++)
                lp[t][k] += __shfl_xor_sync(0xffffffffu, lp[t][k], off);

    const float scale = 0.044194173824159216f;  // 1/sqrt(512)
#pragma unroll
    for (int t = 0; t < 8; t++) {
        float l[8];
        float m = -3.4e38f;
#pragma unroll
        for (int k = 0; k < 8; k++) { l[k] = lp[t][k] * scale; m = fmaxf(m, l[k]); }
        float s = 0.0f;
#pragma unroll
        for (int k = 0; k < 8; k++) { l[k] = __expf(l[k] - m); s += l[k]; }
        float inv = 1.0f / s;
        if (lane == t) {
            float4* a4 = (float4*)(g_attn + ((size_t)b * SS + tok0 + t) * 8);
            a4[0] = make_float4(l[0] * inv, l[1] * inv, l[2] * inv, l[3] * inv);
            a4[1] = make_float4(l[4] * inv, l[5] * inv, l[6] * inv, l[7] * inv);
        }
    }
}

// ---------- Kernel F2: out = x + attn @ RO ----------
__global__ void __launch_bounds__(256) k_out(const float* __restrict__ x,
                                             float* __restrict__ out) {
    __shared__ float ROp[HH * 9];
    __shared__ float attn_sh[64 * 8];
    int b = blockIdx.y;
    const float* ROg = g_RO + (size_t)b * HH * 8;
    for (int i = threadIdx.x; i < HH * 8; i += 256) {
        int h = i >> 3, k = i & 7;
        ROp[h * 9 + k] = ROg[i];
    }
    int tokblk = blockIdx.x * 64;
    for (int i = threadIdx.x; i < 64 * 8; i += 256)
        attn_sh[i] = g_attn[((size_t)b * SS + tokblk) * 8 + i];
    __syncthreads();

    int lane = threadIdx.x & 31, warp = threadIdx.x >> 5;
    int tok0 = warp * 8;
    float att[8][8];
#pragma unroll
    for (int t = 0; t < 8; t++)
#pragma unroll
        for (int k = 0; k < 8; k++) att[t][k] = attn_sh[(tok0 + t) * 8 + k];

    const float* xb = x + ((size_t)b * SS + tokblk + tok0) * HH;
    float* ob = out + ((size_t)b * SS + tokblk + tok0) * HH;

#pragma unroll 2
    for (int i = 0; i < 32; i++) {
        int h = lane + 32 * i;
        float ro[8];
#pragma unroll
        for (int k = 0; k < 8; k++) ro[k] = ROp[h * 9 + k];
#pragma unroll
        for (int t = 0; t < 8; t++) {
            float o = xb[(size_t)t * HH + h];
#pragma unroll
            for (int k = 0; k < 8; k++) o += att[t][k] * ro[k];
            ob[(size_t)t * HH + h] = o;
        }
    }
}

// ---------- launch ----------
extern "C" void kernel_launch(void* const* d_in, const int* in_sizes, int n_in,
                              void* d_out, int out_size) {
    const float* x   = (const float*)d_in[0];
    const float* mem = (const float*)d_in[1];
    const float* Wq  = (const float*)d_in[2];
    const float* Wo  = (const float*)d_in[3];
    // d_in[4] = top_k (always 8; hardcoded)
    float* out = (float*)d_out;

    k_xpart <<<dim3(4, 8, 8),   256>>>(x);
    k_query <<<dim3(2, 8),      256>>>(Wq);
    k_scores<<<8192,            256>>>(mem);
    k_topk1 <<<dim3(TKB, 8),    256>>>();
    k_topk2 <<<8,               128>>>();
    k_gather<<<64,              128>>>(mem);
    k_w2    <<<dim3(4, 8),      256>>>(Wq);
    k_ro    <<<dim3(4, 8),      256>>>(Wo);
    k_attn  <<<dim3(32, 8),     256>>>(x);
    k_out   <<<dim3(32, 8),     256>>>(x, out);
}

// round 6
// speedup vs baseline: 1.1453x; 1.0035x over previous
#include <cuda_runtime.h>
#include <math.h>

#define BB 8
#define SS 2048
#define HH 1024
#define NN 262144
#define DD 512
#define KK 8
#define TKB 128   // top-k stage-1 blocks per batch

// ---------- scratch (device globals; no allocation allowed) ----------
__device__ float g_xpart[8 * BB * HH];      // [z][b][h] partial sums over S
__device__ float g_q[BB * DD];              // pooled (unnormalized) queries
__device__ float g_scores[NN * BB];         // [n][b] cosine scores
__device__ int   g_topk[BB * KK];           // [b][k] indices
__device__ float g_cand_v[BB * TKB * 8];    // stage-1 candidate values
__device__ int   g_cand_i[BB * TKB * 8];    // stage-1 candidate indices
__device__ float g_Rt[BB * DD * KK];        // [b][d][k] normalized retrieved rows (transposed)
__device__ float g_W2[BB * HH * KK];        // [b][h][k] = Wq @ R^T
__device__ float g_RO[BB * HH * KK];        // [b][h][k] = (R @ Wo) stored h-major
__device__ float g_attn[BB * SS * KK];      // [b][s][k] softmax weights

// ---------- packed fp32x2 helpers (sm_100+; ptxas never auto-fuses these) ----------
__device__ __forceinline__ unsigned long long pack2(float lo, float hi) {
    unsigned long long r;
    asm("mov.b64 %0, {%1, %2};" : "=l"(r)
        : "r"(__float_as_uint(lo)), "r"(__float_as_uint(hi)));
    return r;
}
__device__ __forceinline__ void fma2(unsigned long long& d,
                                     unsigned long long a, unsigned long long b) {
    asm("fma.rn.f32x2 %0, %1, %2, %0;" : "+l"(d) : "l"(a), "l"(b));
}
__device__ __forceinline__ void unpack2(unsigned long long v, float& lo, float& hi) {
    unsigned int l, h;
    asm("mov.b64 {%0, %1}, %2;" : "=r"(l), "=r"(h) : "l"(v));
    lo = __uint_as_float(l); hi = __uint_as_float(h);
}

// ---------- Kernel A: partial sums of x over S ----------
__global__ void k_xpart(const float* __restrict__ x) {
    int h = blockIdx.x * 256 + threadIdx.x;  // grid.x = 4
    int b = blockIdx.y;                       // 8
    int z = blockIdx.z;                       // 8 s-chunks of 256
    const float* xp = x + ((size_t)b * SS + (size_t)z * 256) * HH + h;
    float s = 0.0f;
#pragma unroll 8
    for (int i = 0; i < 256; i++) s += xp[(size_t)i * HH];
    g_xpart[(z * BB + b) * HH + h] = s;
}

// ---------- Kernel B: q[b][d] = (sum_s x[b,s,:]) @ Wq ----------
__global__ void k_query(const float* __restrict__ Wq) {
    __shared__ float xs[HH];
    int b = blockIdx.y;
    for (int h = threadIdx.x; h < HH; h += 256) {
        float s = 0.0f;
#pragma unroll
        for (int z = 0; z < 8; z++) s += g_xpart[(z * BB + b) * HH + h];
        xs[h] = s;
    }
    __syncthreads();
    int d = blockIdx.x * 256 + threadIdx.x;  // grid.x = 2
    float acc = 0.0f;
#pragma unroll 4
    for (int h = 0; h < HH; h++) acc += xs[h] * Wq[(size_t)h * DD + d];
    g_q[b * DD + d] = acc;
}

// ---------- Kernel C: cosine scores over the 512MB archive ----------
// warp handles 4 rows; batch-PAIR-packed f32x2 accumulators halve fp32-pipe ops.
// q2_sh layout [bp][c][d4] (u64 = (q[2bp][d],q[2bp+1][d])) -> LDS.64, conflict-free.
__global__ void __launch_bounds__(256) k_scores(const float* __restrict__ mem) {
    __shared__ unsigned long long q2_sh[4 * 4 * 128];  // 16KB
    int tid = threadIdx.x;
    for (int i = tid; i < 2048; i += 256) {
        int d4 = i & 127;
        int c  = (i >> 7) & 3;
        int bp = i >> 9;
        int d  = d4 * 4 + c;
        q2_sh[i] = pack2(g_q[(2 * bp) * DD + d], g_q[(2 * bp + 1) * DD + d]);
    }
    __syncthreads();

    int lane = tid & 31, warp = tid >> 5;
    size_t row0 = ((size_t)blockIdx.x * 8 + warp) * 4;
    const float4* m4 = (const float4*)mem;

    unsigned long long acc2[4][4];  // [row][batch-pair]
    float nrm[4];
#pragma unroll
    for (int r = 0; r < 4; r++) {
        nrm[r] = 0.0f;
#pragma unroll
        for (int bp = 0; bp < 4; bp++) acc2[r][bp] = 0ull;
    }

#pragma unroll 2
    for (int j = 0; j < 4; j++) {
        int d4 = lane + 32 * j;  // float4 index 0..127
        float4 m[4];
#pragma unroll
        for (int r = 0; r < 4; r++) m[r] = m4[(row0 + r) * (DD / 4) + d4];
#pragma unroll
        for (int r = 0; r < 4; r++)
            nrm[r] += m[r].x * m[r].x + m[r].y * m[r].y + m[r].z * m[r].z + m[r].w * m[r].w;

        // duplicate m per row/component once, reuse across 4 batch pairs
        unsigned long long md[4][4];
#pragma unroll
        for (int r = 0; r < 4; r++) {
            md[r][0] = pack2(m[r].x, m[r].x);
            md[r][1] = pack2(m[r].y, m[r].y);
            md[r][2] = pack2(m[r].z, m[r].z);
            md[r][3] = pack2(m[r].w, m[r].w);
        }
#pragma unroll
        for (int bp = 0; bp < 4; bp++) {
            unsigned long long q0 = q2_sh[(bp * 4 + 0) * 128 + d4];
            unsigned long long q1 = q2_sh[(bp * 4 + 1) * 128 + d4];
            unsigned long long q2 = q2_sh[(bp * 4 + 2) * 128 + d4];
            unsigned long long q3 = q2_sh[(bp * 4 + 3) * 128 + d4];
#pragma unroll
            for (int r = 0; r < 4; r++) {
                fma2(acc2[r][bp], md[r][0], q0);
                fma2(acc2[r][bp], md[r][1], q1);
                fma2(acc2[r][bp], md[r][2], q2);
                fma2(acc2[r][bp], md[r][3], q3);
            }
        }
    }

    float acc[4][8];
#pragma unroll
    for (int r = 0; r < 4; r++)
#pragma unroll
        for (int bp = 0; bp < 4; bp++)
            unpack2(acc2[r][bp], acc[r][2 * bp], acc[r][2 * bp + 1]);

#pragma unroll
    for (int off = 16; off; off >>= 1) {
#pragma unroll
        for (int r = 0; r < 4; r++) {
            nrm[r] += __shfl_down_sync(0xffffffffu, nrm[r], off);
#pragma unroll
            for (int b = 0; b < 8; b++)
                acc[r][b] += __shfl_down_sync(0xffffffffu, acc[r][b], off);
        }
    }
    if (lane == 0) {
#pragma unroll
        for (int r = 0; r < 4; r++) {
            float inv = 1.0f / (sqrtf(nrm[r]) + 1e-8f);
            float4* s4 = (float4*)&g_scores[(row0 + r) * 8];
            s4[0] = make_float4(acc[r][0] * inv, acc[r][1] * inv, acc[r][2] * inv, acc[r][3] * inv);
            s4[1] = make_float4(acc[r][4] * inv, acc[r][5] * inv, acc[r][6] * inv, acc[r][7] * inv);
        }
    }
}

// ---------- Kernel D1: stage-1 top-8 (128 slices x 8 batches = 1024 blocks) ----------
__global__ void __launch_bounds__(256) k_topk1() {
    __shared__ float sv[256 * 8];
    __shared__ int   si[256 * 8];
    int b = blockIdx.y, blk = blockIdx.x, tid = threadIdx.x;
    int base = blk * (NN / TKB);  // 2048 rows per block

    float vals[8];
    int idxs[8];
#pragma unroll
    for (int i = 0; i < 8; i++) { vals[i] = -3.4e38f; idxs[i] = 0; }
    float vmin = -3.4e38f;

#pragma unroll 2
    for (int i = tid; i < NN / TKB; i += 256) {
        int n = base + i;
        float v = g_scores[(size_t)n * 8 + b];
        if (v > vmin) {
            vals[7] = v; idxs[7] = n;
#pragma unroll
            for (int p = 7; p >= 1; p--) {
                if (vals[p] > vals[p - 1]) {
                    float tv = vals[p]; vals[p] = vals[p - 1]; vals[p - 1] = tv;
                    int ti = idxs[p]; idxs[p] = idxs[p - 1]; idxs[p - 1] = ti;
                }
            }
            vmin = vals[7];
        }
    }
#pragma unroll
    for (int i = 0; i < 8; i++) { sv[tid * 8 + i] = vals[i]; si[tid * 8 + i] = idxs[i]; }

    for (int stride = 128; stride >= 1; stride >>= 1) {
        __syncthreads();
        if (tid < stride) {
            float ov[8]; int oi[8];
            int ia = 0, ib2 = 0;
#pragma unroll
            for (int o = 0; o < 8; o++) {
                float va = sv[tid * 8 + ia];
                float vb = sv[(tid + stride) * 8 + ib2];
                if (va >= vb) { ov[o] = va; oi[o] = si[tid * 8 + ia]; ia++; }
                else          { ov[o] = vb; oi[o] = si[(tid + stride) * 8 + ib2]; ib2++; }
            }
#pragma unroll
            for (int o = 0; o < 8; o++) { sv[tid * 8 + o] = ov[o]; si[tid * 8 + o] = oi[o]; }
        }
    }
    __syncthreads();
    if (tid < 8) {
        g_cand_v[(b * TKB + blk) * 8 + tid] = sv[tid];
        g_cand_i[(b * TKB + blk) * 8 + tid] = si[tid];
    }
}

// ---------- Kernel D2: stage-2 merge of 128 sorted candidate lists per batch ----------
__global__ void __launch_bounds__(128) k_topk2() {
    __shared__ float sv[128 * 8];
    __shared__ int   si[128 * 8];
    int b = blockIdx.x, tid = threadIdx.x;
#pragma unroll
    for (int i = 0; i < 8; i++) {
        sv[tid * 8 + i] = g_cand_v[(b * TKB + tid) * 8 + i];
        si[tid * 8 + i] = g_cand_i[(b * TKB + tid) * 8 + i];
    }
    for (int stride = 64; stride >= 1; stride >>= 1) {
        __syncthreads();
        if (tid < stride) {
            float ov[8]; int oi[8];
            int ia = 0, ib2 = 0;
#pragma unroll
            for (int o = 0; o < 8; o++) {
                float va = sv[tid * 8 + ia];
                float vb = sv[(tid + stride) * 8 + ib2];
                if (va >= vb) { ov[o] = va; oi[o] = si[tid * 8 + ia]; ia++; }
                else          { ov[o] = vb; oi[o] = si[(tid + stride) * 8 + ib2]; ib2++; }
            }
#pragma unroll
            for (int o = 0; o < 8; o++) { sv[tid * 8 + o] = ov[o]; si[tid * 8 + o] = oi[o]; }
        }
    }
    __syncthreads();
    if (tid < 8) g_topk[b * 8 + tid] = si[tid];
}

// ---------- Kernel E1: gather + normalize retrieved rows -> g_Rt [b][d][k] ----------
__global__ void k_gather(const float* __restrict__ mem) {
    int g = blockIdx.x;  // b*8+k, 64 blocks
    int b = g >> 3, k = g & 7;
    int row = g_topk[g];
    const float4* m4 = (const float4*)(mem + (size_t)row * DD);
    __shared__ float red[128];
    int tid = threadIdx.x;  // 128 threads
    float4 v = m4[tid];
    red[tid] = v.x * v.x + v.y * v.y + v.z * v.z + v.w * v.w;
    __syncthreads();
    for (int s = 64; s; s >>= 1) {
        if (tid < s) red[tid] += red[tid + s];
        __syncthreads();
    }
    float inv = 1.0f / (sqrtf(red[0]) + 1e-8f);
    int d0 = tid * 4;
    float* Rt = g_Rt + (size_t)b * DD * 8;
    Rt[(d0 + 0) * 8 + k] = v.x * inv;
    Rt[(d0 + 1) * 8 + k] = v.y * inv;
    Rt[(d0 + 2) * 8 + k] = v.z * inv;
    Rt[(d0 + 3) * 8 + k] = v.w * inv;
}

// ---------- Kernel E2: W2[b][h][k] = sum_d Wq[h][d] * R[b][k][d] ----------
__global__ void __launch_bounds__(256) k_w2(const float* __restrict__ Wq) {
    __shared__ float4 R_sh[DD * 2];  // [d] -> 2x float4 over k
    int b = blockIdx.y;
    const float4* Rt4 = (const float4*)(g_Rt + (size_t)b * DD * 8);
    for (int i = threadIdx.x; i < DD * 2; i += 256) R_sh[i] = Rt4[i];
    __syncthreads();

    int h = blockIdx.x * 256 + threadIdx.x;  // grid.x = 4
    const float4* wq4 = (const float4*)(Wq + (size_t)h * DD);
    float acc[8];
#pragma unroll
    for (int k = 0; k < 8; k++) acc[k] = 0.0f;
#pragma unroll 2
    for (int dd = 0; dd < DD / 4; dd++) {
        float4 w = wq4[dd];
        float wv[4] = {w.x, w.y, w.z, w.w};
#pragma unroll
        for (int c = 0; c < 4; c++) {
            float4 r0 = R_sh[(dd * 4 + c) * 2];
            float4 r1 = R_sh[(dd * 4 + c) * 2 + 1];
            acc[0] += wv[c] * r0.x; acc[1] += wv[c] * r0.y;
            acc[2] += wv[c] * r0.z; acc[3] += wv[c] * r0.w;
            acc[4] += wv[c] * r1.x; acc[5] += wv[c] * r1.y;
            acc[6] += wv[c] * r1.z; acc[7] += wv[c] * r1.w;
        }
    }
    float4* o = (float4*)(g_W2 + ((size_t)b * HH + h) * 8);
    o[0] = make_float4(acc[0], acc[1], acc[2], acc[3]);
    o[1] = make_float4(acc[4], acc[5], acc[6], acc[7]);
}

// ---------- Kernel E3: RO[b][h][k] = sum_d R[b][k][d] * Wo[d][h] ----------
__global__ void __launch_bounds__(256) k_ro(const float* __restrict__ Wo) {
    __shared__ float4 R_sh[DD * 2];
    int b = blockIdx.y;
    const float4* Rt4 = (const float4*)(g_Rt + (size_t)b * DD * 8);
    for (int i = threadIdx.x; i < DD * 2; i += 256) R_sh[i] = Rt4[i];
    __syncthreads();

    int h = blockIdx.x * 256 + threadIdx.x;
    float acc[8];
#pragma unroll
    for (int k = 0; k < 8; k++) acc[k] = 0.0f;
#pragma unroll 4
    for (int d = 0; d < DD; d++) {
        float wo = Wo[(size_t)d * HH + h];
        float4 r0 = R_sh[d * 2];
        float4 r1 = R_sh[d * 2 + 1];
        acc[0] += wo * r0.x; acc[1] += wo * r0.y; acc[2] += wo * r0.z; acc[3] += wo * r0.w;
        acc[4] += wo * r1.x; acc[5] += wo * r1.y; acc[6] += wo * r1.z; acc[7] += wo * r1.w;
    }
    float4* o = (float4*)(g_RO + ((size_t)b * HH + h) * 8);
    o[0] = make_float4(acc[0], acc[1], acc[2], acc[3]);
    o[1] = make_float4(acc[4], acc[5], acc[6], acc[7]);
}

// ---------- Kernel F1: logits = x @ W2 / sqrt(D), softmax -> g_attn ----------
__global__ void __launch_bounds__(256) k_attn(const float* __restrict__ x) {
    __shared__ float W2p[HH * 9];  // padded stride 9 -> conflict-free
    int b = blockIdx.y;
    const float* W2g = g_W2 + (size_t)b * HH * 8;
    for (int i = threadIdx.x; i < HH * 8; i += 256) {
        int h = i >> 3, k = i & 7;
        W2p[h * 9 + k] = W2g[i];
    }
    __syncthreads();

    int lane = threadIdx.x & 31, warp = threadIdx.x >> 5;
    int tok0 = blockIdx.x * 64 + warp * 8;  // grid.x = 32
    const float* xb = x + ((size_t)b * SS + tok0) * HH;

    float lp[8][8];
#pragma unroll
    for (int t = 0; t < 8; t++)
#pragma unroll
        for (int k = 0; k < 8; k++) lp[t][k] = 0.0f;

#pragma unroll 4
    for (int i = 0; i < 32; i++) {
        int h = lane + 32 * i;
        float w2v[8];
#pragma unroll
        for (int k = 0; k < 8; k++) w2v[k] = W2p[h * 9 + k];
#pragma unroll
        for (int t = 0; t < 8; t++) {
            float xv = xb[(size_t)t * HH + h];
#pragma unroll
            for (int k = 0; k < 8; k++) lp[t][k] += xv * w2v[k];
        }
    }
#pragma unroll
    for (int off = 16; off; off >>= 1)
#pragma unroll
        for (int t = 0; t < 8; t++)
#pragma unroll
            for (int k = 0; k < 8; k++)
                lp[t][k] += __shfl_xor_sync(0xffffffffu, lp[t][k], off);

    const float scale = 0.044194173824159216f;  // 1/sqrt(512)
#pragma unroll
    for (int t = 0; t < 8; t++) {
        float l[8];
        float m = -3.4e38f;
#pragma unroll
        for (int k = 0; k < 8; k++) { l[k] = lp[t][k] * scale; m = fmaxf(m, l[k]); }
        float s = 0.0f;
#pragma unroll
        for (int k = 0; k < 8; k++) { l[k] = __expf(l[k] - m); s += l[k]; }
        float inv = 1.0f / s;
        if (lane == t) {
            float4* a4 = (float4*)(g_attn + ((size_t)b * SS + tok0 + t) * 8);
            a4[0] = make_float4(l[0] * inv, l[1] * inv, l[2] * inv, l[3] * inv);
            a4[1] = make_float4(l[4] * inv, l[5] * inv, l[6] * inv, l[7] * inv);
        }
    }
}

// ---------- Kernel F2: out = x + attn @ RO ----------
__global__ void __launch_bounds__(256) k_out(const float* __restrict__ x,
                                             float* __restrict__ out) {
    __shared__ float ROp[HH * 9];
    __shared__ float attn_sh[64 * 8];
    int b = blockIdx.y;
    const float* ROg = g_RO + (size_t)b * HH * 8;
    for (int i = threadIdx.x; i < HH * 8; i += 256) {
        int h = i >> 3, k = i & 7;
        ROp[h * 9 + k] = ROg[i];
    }
    int tokblk = blockIdx.x * 64;
    for (int i = threadIdx.x; i < 64 * 8; i += 256)
        attn_sh[i] = g_attn[((size_t)b * SS + tokblk) * 8 + i];
    __syncthreads();

    int lane = threadIdx.x & 31, warp = threadIdx.x >> 5;
    int tok0 = warp * 8;
    float att[8][8];
#pragma unroll
    for (int t = 0; t < 8; t++)
#pragma unroll
        for (int k = 0; k < 8; k++) att[t][k] = attn_sh[(tok0 + t) * 8 + k];

    const float* xb = x + ((size_t)b * SS + tokblk + tok0) * HH;
    float* ob = out + ((size_t)b * SS + tokblk + tok0) * HH;

#pragma unroll 2
    for (int i = 0; i < 32; i++) {
        int h = lane + 32 * i;
        float ro[8];
#pragma unroll
        for (int k = 0; k < 8; k++) ro[k] = ROp[h * 9 + k];
#pragma unroll
        for (int t = 0; t < 8; t++) {
            float o = xb[(size_t)t * HH + h];
#pragma unroll
            for (int k = 0; k < 8; k++) o += att[t][k] * ro[k];
            ob[(size_t)t * HH + h] = o;
        }
    }
}

// ---------- launch ----------
extern "C" void kernel_launch(void* const* d_in, const int* in_sizes, int n_in,
                              void* d_out, int out_size) {
    const float* x   = (const float*)d_in[0];
    const float* mem = (const float*)d_in[1];
    const float* Wq  = (const float*)d_in[2];
    const float* Wo  = (const float*)d_in[3];
    // d_in[4] = top_k (always 8; hardcoded)
    float* out = (float*)d_out;

    k_xpart <<<dim3(4, 8, 8),   256>>>(x);
    k_query <<<dim3(2, 8),      256>>>(Wq);
    k_scores<<<8192,            256>>>(mem);
    k_topk1 <<<dim3(TKB, 8),    256>>>();
    k_topk2 <<<8,               128>>>();
    k_gather<<<64,              128>>>(mem);
    k_w2    <<<dim3(4, 8),      256>>>(Wq);
    k_ro    <<<dim3(4, 8),      256>>>(Wo);
    k_attn  <<<dim3(32, 8),     256>>>(x);
    k_out   <<<dim3(32, 8),     256>>>(x, out);
}